// round 13
// baseline (speedup 1.0000x reference)
#include <cuda_runtime.h>
#include <cuda_fp16.h>
#include <math.h>

#define Bn 4
#define Nn 2048
#define IND 128
#define Hn 4
#define Dn 64
#define C 256   // H*D
#define ROWS (Bn*Nn)   // 8192
#define LOG2E 1.4426950408889634f

// ---- scratch (static device globals; no allocation) ----
__device__ float g_Wh[ROWS*C];                    // [B*N, 256] fp32
__device__ unsigned int g_WhT[Bn*Hn*Dn*Nn/2];     // fp16 pairs, [b][h][d][n]
__device__ unsigned char g_maskb[(size_t)Nn*Nn];  // 0xFF / 0x00 per (i,j)
__device__ float g_src[Bn*Hn*Nn];                 // pre-scaled by LOG2E
__device__ float g_dst[Bn*Hn*Nn];                 // pre-scaled by LOG2E
__device__ float g_part[2][ROWS*C];               // unnormalized numerators per j-half
__device__ float g_rsp[2][Bn*Hn*Nn];              // partial rowsums per j-half
__device__ float g_hnew[ROWS*C];
__device__ float g_psum[256*C];
__device__ float g_psq[256*C];
__device__ float g_mean[C];
__device__ float g_rstd[C];

__device__ __forceinline__ float ex2(float x) {
    float r;
    asm("ex2.approx.f32 %0, %1;" : "=f"(r) : "f"(x));
    return r;
}
__device__ __forceinline__ unsigned int packh2(float a, float b) {
    __half2 h = __floats2half2_rn(a, b);   // low = a, high = b
    return *(unsigned int*)&h;
}
__device__ __forceinline__ void mma_f16(float* c,
                                        unsigned int a0, unsigned int a1,
                                        unsigned int a2, unsigned int a3,
                                        unsigned int b0, unsigned int b1) {
    asm("mma.sync.aligned.m16n8k16.row.col.f32.f16.f16.f32 "
        "{%0,%1,%2,%3}, {%4,%5,%6,%7}, {%8,%9}, {%0,%1,%2,%3};"
        : "+f"(c[0]), "+f"(c[1]), "+f"(c[2]), "+f"(c[3])
        : "r"(a0), "r"(a1), "r"(a2), "r"(a3), "r"(b0), "r"(b1));
}
__device__ __forceinline__ void cp16(unsigned int saddr, const void* gptr) {
    asm volatile("cp.async.cg.shared.global [%0], [%1], 16;" :: "r"(saddr), "l"(gptr));
}
__device__ __forceinline__ void cp4(unsigned int saddr, const void* gptr) {
    asm volatile("cp.async.ca.shared.global [%0], [%1], 4;" :: "r"(saddr), "l"(gptr));
}
__device__ __forceinline__ int sigma3(int g) {   // chunk-swizzle: {0,4,1,5,2,6,3,7}
    return ((g & 1) << 2) | (g >> 1);
}

// ============================================================
// K1: Wh = h @ W ; also emit transposed fp16 copy g_WhT[b][h][d][n]
// ============================================================
__global__ __launch_bounds__(256) void k_gemm(const float* __restrict__ hIn,
                                              const float* __restrict__ W) {
    __shared__ float hs[32 * IND];
    int row0 = blockIdx.x * 32;
    const float4* gp = (const float4*)(hIn + (size_t)row0 * IND);
    float4* sp = (float4*)hs;
    for (int i = threadIdx.x; i < 32 * IND / 4; i += 256) sp[i] = gp[i];
    __syncthreads();

    int c = threadIdx.x;
    float acc[32];
#pragma unroll
    for (int r = 0; r < 32; r++) acc[r] = 0.f;

    for (int k = 0; k < IND; k += 4) {
        float w0 = __ldg(&W[(k + 0) * C + c]);
        float w1 = __ldg(&W[(k + 1) * C + c]);
        float w2 = __ldg(&W[(k + 2) * C + c]);
        float w3 = __ldg(&W[(k + 3) * C + c]);
#pragma unroll
        for (int r = 0; r < 32; r++) {
            float4 hv = *(const float4*)&hs[r * IND + k];
            acc[r] += hv.x * w0 + hv.y * w1 + hv.z * w2 + hv.w * w3;
        }
    }
#pragma unroll
    for (int r = 0; r < 32; r++) g_Wh[(size_t)(row0 + r) * C + c] = acc[r];

    // transposed fp16 copy (rows stay inside one b: 2048 % 32 == 0)
    int b = row0 >> 11;
    int n0 = row0 & (Nn - 1);
    int hh = c >> 6, d = c & 63;
    unsigned int* wt = g_WhT + ((size_t)(((b * Hn + hh) * Dn + d)) * Nn + n0) / 2;
    unsigned int wbuf[16];
#pragma unroll
    for (int m = 0; m < 16; m++) wbuf[m] = packh2(acc[2 * m], acc[2 * m + 1]);
#pragma unroll
    for (int q = 0; q < 4; q++) ((uint4*)wt)[q] = ((uint4*)wbuf)[q];
}

// ============================================================
// K2: src/dst projections (pre-scaled by LOG2E). One warp per (b,n,h).
// ============================================================
__global__ __launch_bounds__(256) void k_srcdst(const float* __restrict__ a) {
    int gw = blockIdx.x * 8 + (threadIdx.x >> 5);
    int lane = threadIdx.x & 31;
    int hh = gw & 3;
    int n  = (gw >> 2) & (Nn - 1);
    int b  = gw >> 13;
    const float2 v  = ((const float2*)(g_Wh + (size_t)(b * Nn + n) * C + hh * Dn))[lane];
    const float2 a1 = ((const float2*)(a + hh * 2 * Dn))[lane];
    const float2 a2 = ((const float2*)(a + hh * 2 * Dn + Dn))[lane];
    float s = v.x * a1.x + v.y * a1.y;
    float d = v.x * a2.x + v.y * a2.y;
#pragma unroll
    for (int o = 16; o > 0; o >>= 1) {
        s += __shfl_xor_sync(0xffffffffu, s, o);
        d += __shfl_xor_sync(0xffffffffu, d, o);
    }
    if (lane == 0) {
        g_src[(b * Hn + hh) * Nn + n] = s * LOG2E;
        g_dst[(b * Hn + hh) * Nn + n] = d * LOG2E;
    }
}

// ============================================================
// K2b: expand adjacency into byte masks (0xFF / 0x00)
// ============================================================
__global__ __launch_bounds__(256) void k_maskexp(const int* __restrict__ adj) {
    int idx = blockIdx.x * 256 + threadIdx.x;
    const int4* ap = (const int4*)adj + (size_t)idx * 4;
    unsigned int u[4];
#pragma unroll
    for (int q = 0; q < 4; q++) {
        int4 a = ap[q];
        u[q] = (a.x ? 0xFFu : 0u) | (a.y ? 0xFF00u : 0u)
             | (a.z ? 0xFF0000u : 0u) | (a.w ? 0xFF000000u : 0u);
    }
    ((uint4*)g_maskb)[idx] = *(uint4*)u;
}

// ============================================================
// K3: attention, split over j. Grid (32,4,4) = 512 blocks x 128 thr.
// blockIdx.x: bits[4:1] = i-tile (128 i), bit 0 = j-half (1024 j).
// 4 warps, each m32 x 64d, fp16 mma.m16n8k16; byte-mask via PRMT;
// rowsum via B=ones MMAs. Outputs UNNORMALIZED numerator + partial
// rowsum; combination happens in k_bn_partial.
// ============================================================
__global__ __launch_bounds__(128, 3) void k_attn() {
    __shared__ unsigned int WhT_s[2][64 * 32];       // fp16 pairs: [d][j/2], 8 KB each
    __shared__ float dst_s[2][64];
    __shared__ unsigned char maskb_s[2][128 * 64];   // [i][j] bytes, 8 KB each

    int b  = blockIdx.z, hh = blockIdx.y;
    int i0 = (blockIdx.x >> 1) * 128;
    int jh = blockIdx.x & 1;
    int jbase = jh << 10;                            // 0 or 1024
    int t  = threadIdx.x;
    int w  = t >> 5, lane = t & 31;
    int gid = lane >> 2, tig = lane & 3;
    int sg = sigma3(gid);
    const unsigned int BONES = 0x3C003C00u;   // half2(1.0, 1.0)

    int ibase = 32 * w + gid;
    const float* sb = g_src + (b * Hn + hh) * Nn + i0;
    float srcv[4];
#pragma unroll
    for (int rr = 0; rr < 4; rr++) srcv[rr] = sb[ibase + 8 * rr];

    float accA[8][4], accB[8][4];
    float accR[2][4];
#pragma unroll
    for (int dt = 0; dt < 8; dt++)
#pragma unroll
        for (int r = 0; r < 4; r++) { accA[dt][r] = 0.f; accB[dt][r] = 0.f; }
#pragma unroll
    for (int r = 0; r < 4; r++) { accR[0][r] = 0.f; accR[1][r] = 0.f; }

    const unsigned int* WhTg = g_WhT + (size_t)((b * Hn + hh) * Dn) * (Nn / 2);
    const float* db = g_dst + (b * Hn + hh) * Nn;
    const unsigned char* mg0 = g_maskb + (size_t)(i0 + t) * Nn + jbase;

    // staging mapping: Wh row d_l = t>>1, chunk-quad c2 = t&1
    int d_l = t >> 1, c2 = t & 1;
    int sgs = sigma3(d_l & 7);
    int tsw = t & 3;                     // mask staging chunk-swizzle for row t

    unsigned int whbase = (unsigned int)__cvta_generic_to_shared(&WhT_s[0][0]);
    unsigned int dstaddr0 = (unsigned int)__cvta_generic_to_shared(&dst_s[0][t & 63]);
    unsigned int mskbase = (unsigned int)__cvta_generic_to_shared(&maskb_s[0][0]);
    const unsigned int WHSTRIDE = 64 * 32 * 4;       // 8 KB
    const unsigned int MSKSTRIDE = 128 * 64;         // 8 KB
    const unsigned int DSTSTRIDE = (unsigned int)((char*)&dst_s[1][0] - (char*)&dst_s[0][0]);

    // mask read offsets: row r=ibase+8rr, logical chunk 2v+(tig>>1), phys ^= r&3
    int moff[4][2];
#pragma unroll
    for (int rr = 0; rr < 4; rr++) {
        int r = ibase + 8 * rr;
#pragma unroll
        for (int v = 0; v < 2; v++) {
            int ch = 2 * v + (tig >> 1);
            moff[rr][v] = r * 64 + ((ch ^ (r & 3)) << 4) + 8 * (tig & 1);
        }
    }

    // ---- stage tile 0 into buffer 0 ----
    {
        const unsigned int* gsrc = WhTg + (size_t)d_l * (Nn / 2) + jbase / 2;
        unsigned int srow = whbase + d_l * 128;
#pragma unroll
        for (int u = 0; u < 4; u++) {
            int ch = 4 * c2 + u;
            cp16(srow + 16 * (ch ^ sgs), gsrc + 4 * ch);
        }
        unsigned int mrow = mskbase + t * 64;
#pragma unroll
        for (int ch = 0; ch < 4; ch++)
            cp16(mrow + 16 * (ch ^ tsw), mg0 + 16 * ch);
        if (t < 64) cp4(dstaddr0, db + jbase + t);
        asm volatile("cp.async.commit_group;");
    }

    for (int jt = 0; jt < 16; jt++) {
        int cur = jt & 1;
        asm volatile("cp.async.wait_group 0;");
        __syncthreads();

        // stage next tile (overlaps with compute below)
        if (jt + 1 < 16) {
            int nxt = cur ^ 1;
            int j0n = (jt + 1) * 64;     // offset within this j-half
            const unsigned int* gsrc = WhTg + (size_t)d_l * (Nn / 2) + (jbase + j0n) / 2;
            unsigned int srow = whbase + nxt * WHSTRIDE + d_l * 128;
#pragma unroll
            for (int u = 0; u < 4; u++) {
                int ch = 4 * c2 + u;
                cp16(srow + 16 * (ch ^ sgs), gsrc + 4 * ch);
            }
            unsigned int mrow = mskbase + nxt * MSKSTRIDE + t * 64;
#pragma unroll
            for (int ch = 0; ch < 4; ch++)
                cp16(mrow + 16 * (ch ^ tsw), mg0 + j0n + 16 * ch);
            if (t < 64) cp4(dstaddr0 + nxt * DSTSTRIDE, db + jbase + j0n + t);
            asm volatile("cp.async.commit_group;");
        }

        // ---- phase A: all P for this j-tile, packed + byte-masked ----
        const unsigned char* mtb = &maskb_s[cur][0];
        unsigned int pa[4][4][2];   // [rr][ks][v]
#pragma unroll
        for (int v = 0; v < 2; v++) {
            int jb = 32 * v + 8 * tig;
            float4 dv0 = *(const float4*)&dst_s[cur][jb];
            float4 dv1 = *(const float4*)&dst_s[cur][jb + 4];
            float dj[8] = {dv0.x, dv0.y, dv0.z, dv0.w, dv1.x, dv1.y, dv1.z, dv1.w};
#pragma unroll
            for (int rr = 0; rr < 4; rr++) {
                uint2 mk2 = *(const uint2*)&mtb[moff[rr][v]];
                float sv = srcv[rr];
                float p[8];
#pragma unroll
                for (int c = 0; c < 8; c++) {
                    float e = sv + dj[c];
                    e = fmaxf(e, 0.2f * e);
                    p[c] = ex2(e);
                }
                unsigned int e0 = __byte_perm(mk2.x, 0, 0x1100);
                unsigned int e1 = __byte_perm(mk2.x, 0, 0x3322);
                unsigned int e2 = __byte_perm(mk2.y, 0, 0x1100);
                unsigned int e3 = __byte_perm(mk2.y, 0, 0x3322);
                pa[rr][0][v] = packh2(p[0], p[1]) & e0;
                pa[rr][1][v] = packh2(p[2], p[3]) & e1;
                pa[rr][2][v] = packh2(p[4], p[5]) & e2;
                pa[rr][3][v] = packh2(p[6], p[7]) & e3;
            }
        }

        // ---- rowsum MMAs (B = ones) ----
#pragma unroll
        for (int ks = 0; ks < 4; ks++) {
            mma_f16(accR[0], pa[0][ks][0], pa[1][ks][0], pa[0][ks][1], pa[1][ks][1],
                    BONES, BONES);
            mma_f16(accR[1], pa[2][ks][0], pa[3][ks][0], pa[2][ks][1], pa[3][ks][1],
                    BONES, BONES);
        }

        // ---- phase B: fp16 tensor-core PV ----
        const uint4* tile4 = (const uint4*)&WhT_s[cur][0];
        int c0 = tig ^ sg;
#pragma unroll
        for (int dt = 0; dt < 8; dt++) {
            int rowq = (8 * dt + gid) * 8;
            uint4 v0 = tile4[rowq + c0];
            uint4 v1 = tile4[rowq + (c0 ^ 4)];
            unsigned int bw0[4], bw1[4];
            *(uint4*)bw0 = v0;
            *(uint4*)bw1 = v1;
#pragma unroll
            for (int ks = 0; ks < 4; ks++) {
                mma_f16(accA[dt], pa[0][ks][0], pa[1][ks][0], pa[0][ks][1], pa[1][ks][1],
                        bw0[ks], bw1[ks]);
                mma_f16(accB[dt], pa[2][ks][0], pa[3][ks][0], pa[2][ks][1], pa[3][ks][1],
                        bw0[ks], bw1[ks]);
            }
        }
    }

    // partial rowsums (B=ones makes all cols equal; cols 0/2 = rows rr, rr+1)
    float rsv[4] = {accR[0][0], accR[0][2], accR[1][0], accR[1][2]};
    if (tig == 0) {
        float* rsp = g_rsp[jh] + (b * Hn + hh) * Nn + i0 + ibase;
#pragma unroll
        for (int rr = 0; rr < 4; rr++) rsp[8 * rr] = rsv[rr];
    }

    // store UNNORMALIZED numerators to this half's partial buffer
#pragma unroll
    for (int rr = 0; rr < 4; rr++) {
        float* o = g_part[jh] + (size_t)(b * Nn + i0 + ibase + 8 * rr) * C + hh * Dn;
        float (*ac)[4] = (rr < 2) ? accA : accB;
        int sel = 2 * (rr & 1);
#pragma unroll
        for (int dt = 0; dt < 8; dt++) {
            int d = 8 * dt + 2 * tig;
            *(float2*)&o[d] = make_float2(ac[dt][sel], ac[dt][sel + 1]);
        }
    }
}

// ============================================================
// K4: combine j-halves + BatchNorm partial stats (fused)
// ============================================================
__global__ __launch_bounds__(256) void k_bn_partial() {
    int c = threadIdx.x;
    int hh = c >> 6;
    int r0 = blockIdx.x * 32;
    float s = 0.f, ss = 0.f;
#pragma unroll 4
    for (int r = 0; r < 32; r++) {
        int row = r0 + r;
        int b = row >> 11, n = row & (Nn - 1);
        int ri = (b * Hn + hh) * Nn + n;
        float rsum = g_rsp[0][ri] + g_rsp[1][ri];
        float inv = rsum > 0.f ? 1.f / rsum : 0.f;
        size_t off = (size_t)row * C + c;
        float x = (g_part[0][off] + g_part[1][off]) * inv;
        g_hnew[off] = x;
        s += x; ss += x * x;
    }
    g_psum[blockIdx.x * C + c] = s;
    g_psq [blockIdx.x * C + c] = ss;
}

__global__ __launch_bounds__(256) void k_bn_final() {
    int c = threadIdx.x;
    float s = 0.f, ss = 0.f;
#pragma unroll 8
    for (int k = 0; k < 256; k++) {
        s  += g_psum[k * C + c];
        ss += g_psq [k * C + c];
    }
    float m = s * (1.f / (float)ROWS);
    float v = ss * (1.f / (float)ROWS) - m * m;
    v = v > 0.f ? v : 0.f;
    g_mean[c] = m;
    g_rstd[c] = rsqrtf(v + 1e-5f);
}

// ============================================================
// K6: normalize + affine + ELU
// ============================================================
__global__ __launch_bounds__(256) void k_norm(const float* __restrict__ gamma,
                                              const float* __restrict__ beta,
                                              float* __restrict__ out) {
    int idx = blockIdx.x * 256 + threadIdx.x;
    int c = (idx & 63) * 4;
    float4 x = ((const float4*)g_hnew)[idx];
    float4 y;
    y.x = (x.x - g_mean[c + 0]) * g_rstd[c + 0] * gamma[c + 0] + beta[c + 0];
    y.y = (x.y - g_mean[c + 1]) * g_rstd[c + 1] * gamma[c + 1] + beta[c + 1];
    y.z = (x.z - g_mean[c + 2]) * g_rstd[c + 2] * gamma[c + 2] + beta[c + 2];
    y.w = (x.w - g_mean[c + 3]) * g_rstd[c + 3] * gamma[c + 3] + beta[c + 3];
    y.x = y.x > 0.f ? y.x : expm1f(y.x);
    y.y = y.y > 0.f ? y.y : expm1f(y.y);
    y.z = y.z > 0.f ? y.z : expm1f(y.z);
    y.w = y.w > 0.f ? y.w : expm1f(y.w);
    ((float4*)out)[idx] = y;
}

// ============================================================
extern "C" void kernel_launch(void* const* d_in, const int* in_sizes, int n_in,
                              void* d_out, int out_size) {
    const float* h     = (const float*)d_in[0];
    const float* W     = (const float*)d_in[1];
    const float* a     = (const float*)d_in[2];
    const float* gamma = (const float*)d_in[3];
    const float* beta  = (const float*)d_in[4];
    const int*   adj   = (const int*)d_in[5];
    float* out = (float*)d_out;

    k_gemm<<<ROWS / 32, 256>>>(h, W);
    k_srcdst<<<Bn * Nn * Hn / 8, 256>>>(a);
    k_maskexp<<<Nn * Nn / 16 / 256, 256>>>(adj);
    dim3 g(2 * Nn / 128, Hn, Bn);      // 32 x 4 x 4 = 512 blocks, launch #4 for ncu
    k_attn<<<g, 128>>>();
    k_bn_partial<<<256, 256>>>();
    k_bn_final<<<1, 256>>>();
    k_norm<<<ROWS * C / 4 / 256, 256>>>(gamma, beta, out);
}

// round 14
// speedup vs baseline: 1.1983x; 1.1983x over previous
#include <cuda_runtime.h>
#include <cuda_fp16.h>
#include <math.h>

#define Bn 4
#define Nn 2048
#define IND 128
#define Hn 4
#define Dn 64
#define C 256   // H*D
#define ROWS (Bn*Nn)   // 8192
#define LOG2E 1.4426950408889634f

// ---- scratch (static device globals; no allocation) ----
__device__ float g_Wh[ROWS*C];                    // [B*N, 256] fp32
__device__ unsigned int g_WhT[Bn*Hn*Dn*Nn/2];     // fp16 pairs, [b][h][d][n]
__device__ unsigned char g_maskb[(size_t)Nn*Nn];  // 0xFF / 0x00 per (i,j)
__device__ float g_src[Bn*Hn*Nn];                 // pre-scaled by LOG2E (fp32)
__device__ unsigned short g_dsth[Bn*Hn*Nn];       // pre-scaled by LOG2E (fp16)
__device__ float g_hnew[ROWS*C];
__device__ float g_psum[256*C];
__device__ float g_psq[256*C];
__device__ float g_mean[C];
__device__ float g_rstd[C];

__device__ __forceinline__ unsigned int packh2(float a, float b) {
    __half2 h = __floats2half2_rn(a, b);   // low = a, high = b
    return *(unsigned int*)&h;
}
__device__ __forceinline__ unsigned int hadd2u(unsigned int a, unsigned int b) {
    unsigned int r;
    asm("add.f16x2 %0, %1, %2;" : "=r"(r) : "r"(a), "r"(b));
    return r;
}
__device__ __forceinline__ unsigned int hmul2u(unsigned int a, unsigned int b) {
    unsigned int r;
    asm("mul.f16x2 %0, %1, %2;" : "=r"(r) : "r"(a), "r"(b));
    return r;
}
__device__ __forceinline__ unsigned int hmax2u(unsigned int a, unsigned int b) {
    unsigned int r;
    asm("max.f16x2 %0, %1, %2;" : "=r"(r) : "r"(a), "r"(b));
    return r;
}
__device__ __forceinline__ unsigned int hex2u(unsigned int a) {
    unsigned int r;
    asm("ex2.approx.f16x2 %0, %1;" : "=r"(r) : "r"(a));
    return r;
}
__device__ __forceinline__ void mma_f16(float* c,
                                        unsigned int a0, unsigned int a1,
                                        unsigned int a2, unsigned int a3,
                                        unsigned int b0, unsigned int b1) {
    asm("mma.sync.aligned.m16n8k16.row.col.f32.f16.f16.f32 "
        "{%0,%1,%2,%3}, {%4,%5,%6,%7}, {%8,%9}, {%0,%1,%2,%3};"
        : "+f"(c[0]), "+f"(c[1]), "+f"(c[2]), "+f"(c[3])
        : "r"(a0), "r"(a1), "r"(a2), "r"(a3), "r"(b0), "r"(b1));
}
__device__ __forceinline__ void cp16(unsigned int saddr, const void* gptr) {
    asm volatile("cp.async.cg.shared.global [%0], [%1], 16;" :: "r"(saddr), "l"(gptr));
}
__device__ __forceinline__ void cp4(unsigned int saddr, const void* gptr) {
    asm volatile("cp.async.ca.shared.global [%0], [%1], 4;" :: "r"(saddr), "l"(gptr));
}
__device__ __forceinline__ int sigma3(int g) {   // chunk-swizzle: {0,4,1,5,2,6,3,7}
    return ((g & 1) << 2) | (g >> 1);
}

// ============================================================
// K1: Wh = h @ W ; also emit transposed fp16 copy g_WhT[b][h][d][n]
// ============================================================
__global__ __launch_bounds__(256) void k_gemm(const float* __restrict__ hIn,
                                              const float* __restrict__ W) {
    __shared__ float hs[32 * IND];
    int row0 = blockIdx.x * 32;
    const float4* gp = (const float4*)(hIn + (size_t)row0 * IND);
    float4* sp = (float4*)hs;
    for (int i = threadIdx.x; i < 32 * IND / 4; i += 256) sp[i] = gp[i];
    __syncthreads();

    int c = threadIdx.x;
    float acc[32];
#pragma unroll
    for (int r = 0; r < 32; r++) acc[r] = 0.f;

    for (int k = 0; k < IND; k += 4) {
        float w0 = __ldg(&W[(k + 0) * C + c]);
        float w1 = __ldg(&W[(k + 1) * C + c]);
        float w2 = __ldg(&W[(k + 2) * C + c]);
        float w3 = __ldg(&W[(k + 3) * C + c]);
#pragma unroll
        for (int r = 0; r < 32; r++) {
            float4 hv = *(const float4*)&hs[r * IND + k];
            acc[r] += hv.x * w0 + hv.y * w1 + hv.z * w2 + hv.w * w3;
        }
    }
#pragma unroll
    for (int r = 0; r < 32; r++) g_Wh[(size_t)(row0 + r) * C + c] = acc[r];

    // transposed fp16 copy (rows stay inside one b: 2048 % 32 == 0)
    int b = row0 >> 11;
    int n0 = row0 & (Nn - 1);
    int hh = c >> 6, d = c & 63;
    unsigned int* wt = g_WhT + ((size_t)(((b * Hn + hh) * Dn + d)) * Nn + n0) / 2;
    unsigned int wbuf[16];
#pragma unroll
    for (int m = 0; m < 16; m++) wbuf[m] = packh2(acc[2 * m], acc[2 * m + 1]);
#pragma unroll
    for (int q = 0; q < 4; q++) ((uint4*)wt)[q] = ((uint4*)wbuf)[q];
}

// ============================================================
// K2: src/dst projections (pre-scaled by LOG2E). One warp per (b,n,h).
// src kept fp32; dst stored fp16 (feeds half2 phase A).
// ============================================================
__global__ __launch_bounds__(256) void k_srcdst(const float* __restrict__ a) {
    int gw = blockIdx.x * 8 + (threadIdx.x >> 5);
    int lane = threadIdx.x & 31;
    int hh = gw & 3;
    int n  = (gw >> 2) & (Nn - 1);
    int b  = gw >> 13;
    const float2 v  = ((const float2*)(g_Wh + (size_t)(b * Nn + n) * C + hh * Dn))[lane];
    const float2 a1 = ((const float2*)(a + hh * 2 * Dn))[lane];
    const float2 a2 = ((const float2*)(a + hh * 2 * Dn + Dn))[lane];
    float s = v.x * a1.x + v.y * a1.y;
    float d = v.x * a2.x + v.y * a2.y;
#pragma unroll
    for (int o = 16; o > 0; o >>= 1) {
        s += __shfl_xor_sync(0xffffffffu, s, o);
        d += __shfl_xor_sync(0xffffffffu, d, o);
    }
    if (lane == 0) {
        int idx = (b * Hn + hh) * Nn + n;
        g_src[idx] = s * LOG2E;
        __half hd = __float2half(d * LOG2E);
        g_dsth[idx] = *(unsigned short*)&hd;
    }
}

// ============================================================
// K2b: expand adjacency into byte masks (0xFF / 0x00)
// ============================================================
__global__ __launch_bounds__(256) void k_maskexp(const int* __restrict__ adj) {
    int idx = blockIdx.x * 256 + threadIdx.x;
    const int4* ap = (const int4*)adj + (size_t)idx * 4;
    unsigned int u[4];
#pragma unroll
    for (int q = 0; q < 4; q++) {
        int4 a = ap[q];
        u[q] = (a.x ? 0xFFu : 0u) | (a.y ? 0xFF00u : 0u)
             | (a.z ? 0xFF0000u : 0u) | (a.w ? 0xFF000000u : 0u);
    }
    ((uint4*)g_maskb)[idx] = *(uint4*)u;
}

// ============================================================
// K3: attention. 256 blocks x 128 thr. CTA tile 128 i x 64 d.
// 4 warps, each m32 x 64d, fp16 mma.m16n8k16.
// Phase A fully in packed f16x2 (add/mul/max/ex2.f16x2) — scores
// are born packed; byte-mask via PRMT + LOP3-AND.
// Rowsum via B=ones MMAs. cp.async double-buffer, one sync/tile.
// ============================================================
__global__ __launch_bounds__(128, 3) void k_attn() {
    __shared__ unsigned int WhT_s[2][64 * 32];       // fp16 pairs: [d][j/2], 8 KB each
    __shared__ unsigned int dsth_s[2][32];           // fp16 pairs of dst (64 j)
    __shared__ unsigned char maskb_s[2][128 * 64];   // [i][j] bytes, 8 KB each

    int b  = blockIdx.z, hh = blockIdx.y;
    int i0 = blockIdx.x * 128;
    int t  = threadIdx.x;
    int w  = t >> 5, lane = t & 31;
    int gid = lane >> 2, tig = lane & 3;
    int sg = sigma3(gid);
    const unsigned int BONES = 0x3C003C00u;   // half2(1.0, 1.0)
    const unsigned int H02   = 0x32663266u;   // half2(0.2, 0.2)

    int ibase = 32 * w + gid;
    const float* sb = g_src + (b * Hn + hh) * Nn + i0;
    unsigned int src2[4];
#pragma unroll
    for (int rr = 0; rr < 4; rr++) {
        float sv = sb[ibase + 8 * rr];
        src2[rr] = packh2(sv, sv);
    }

    float accA[8][4], accB[8][4];
    float accR[2][4];
#pragma unroll
    for (int dt = 0; dt < 8; dt++)
#pragma unroll
        for (int r = 0; r < 4; r++) { accA[dt][r] = 0.f; accB[dt][r] = 0.f; }
#pragma unroll
    for (int r = 0; r < 4; r++) { accR[0][r] = 0.f; accR[1][r] = 0.f; }

    const unsigned int* WhTg = g_WhT + (size_t)((b * Hn + hh) * Dn) * (Nn / 2);
    const unsigned short* db = g_dsth + (b * Hn + hh) * Nn;
    const unsigned char* mg0 = g_maskb + (size_t)(i0 + t) * Nn;

    // staging mapping: Wh row d_l = t>>1, chunk-quad c2 = t&1
    int d_l = t >> 1, c2 = t & 1;
    int sgs = sigma3(d_l & 7);
    int tsw = t & 3;                     // mask staging chunk-swizzle for row t

    unsigned int whbase = (unsigned int)__cvta_generic_to_shared(&WhT_s[0][0]);
    unsigned int dstaddr0 = (unsigned int)__cvta_generic_to_shared(&dsth_s[0][t & 31]);
    unsigned int mskbase = (unsigned int)__cvta_generic_to_shared(&maskb_s[0][0]);
    const unsigned int WHSTRIDE = 64 * 32 * 4;       // 8 KB
    const unsigned int MSKSTRIDE = 128 * 64;         // 8 KB
    const unsigned int DSTSTRIDE = (unsigned int)((char*)&dsth_s[1][0] - (char*)&dsth_s[0][0]);

    // mask read offsets: row r=ibase+8rr, logical chunk 2v+(tig>>1), phys ^= r&3
    int moff[4][2];
#pragma unroll
    for (int rr = 0; rr < 4; rr++) {
        int r = ibase + 8 * rr;
#pragma unroll
        for (int v = 0; v < 2; v++) {
            int ch = 2 * v + (tig >> 1);
            moff[rr][v] = r * 64 + ((ch ^ (r & 3)) << 4) + 8 * (tig & 1);
        }
    }

    // ---- stage tile 0 into buffer 0 ----
    {
        const unsigned int* gsrc = WhTg + (size_t)d_l * (Nn / 2);
        unsigned int srow = whbase + d_l * 128;
#pragma unroll
        for (int u = 0; u < 4; u++) {
            int ch = 4 * c2 + u;
            cp16(srow + 16 * (ch ^ sgs), gsrc + 4 * ch);
        }
        unsigned int mrow = mskbase + t * 64;
#pragma unroll
        for (int ch = 0; ch < 4; ch++)
            cp16(mrow + 16 * (ch ^ tsw), mg0 + 16 * ch);
        if (t < 32) cp4(dstaddr0, db + 2 * t);
        asm volatile("cp.async.commit_group;");
    }

    for (int jt = 0; jt < 32; jt++) {
        int cur = jt & 1;
        asm volatile("cp.async.wait_group 0;");
        __syncthreads();

        // stage next tile (overlaps with compute below)
        if (jt + 1 < 32) {
            int nxt = cur ^ 1;
            int j0n = (jt + 1) * 64;
            const unsigned int* gsrc = WhTg + (size_t)d_l * (Nn / 2) + j0n / 2;
            unsigned int srow = whbase + nxt * WHSTRIDE + d_l * 128;
#pragma unroll
            for (int u = 0; u < 4; u++) {
                int ch = 4 * c2 + u;
                cp16(srow + 16 * (ch ^ sgs), gsrc + 4 * ch);
            }
            unsigned int mrow = mskbase + nxt * MSKSTRIDE + t * 64;
#pragma unroll
            for (int ch = 0; ch < 4; ch++)
                cp16(mrow + 16 * (ch ^ tsw), mg0 + j0n + 16 * ch);
            if (t < 32) cp4(dstaddr0 + nxt * DSTSTRIDE, db + j0n + 2 * t);
            asm volatile("cp.async.commit_group;");
        }

        // ---- phase A: packed f16x2 scores + byte-mask ----
        const unsigned char* mtb = &maskb_s[cur][0];
        unsigned int pa[4][4][2];   // [rr][ks][v]
#pragma unroll
        for (int v = 0; v < 2; v++) {
            // 4 half2 of dst covering j = 32v + 8tig .. +7
            uint4 dh4 = *(const uint4*)&dsth_s[cur][16 * v + 4 * tig];
            unsigned int dh[4];
            *(uint4*)dh = dh4;
#pragma unroll
            for (int rr = 0; rr < 4; rr++) {
                uint2 mk2 = *(const uint2*)&mtb[moff[rr][v]];
                unsigned int e0 = __byte_perm(mk2.x, 0, 0x1100);
                unsigned int e1 = __byte_perm(mk2.x, 0, 0x3322);
                unsigned int e2 = __byte_perm(mk2.y, 0, 0x1100);
                unsigned int e3 = __byte_perm(mk2.y, 0, 0x3322);
                unsigned int s2 = src2[rr];
                unsigned int h0 = hadd2u(s2, dh[0]);
                unsigned int h1 = hadd2u(s2, dh[1]);
                unsigned int h2 = hadd2u(s2, dh[2]);
                unsigned int h3 = hadd2u(s2, dh[3]);
                h0 = hmax2u(h0, hmul2u(h0, H02));
                h1 = hmax2u(h1, hmul2u(h1, H02));
                h2 = hmax2u(h2, hmul2u(h2, H02));
                h3 = hmax2u(h3, hmul2u(h3, H02));
                pa[rr][0][v] = hex2u(h0) & e0;
                pa[rr][1][v] = hex2u(h1) & e1;
                pa[rr][2][v] = hex2u(h2) & e2;
                pa[rr][3][v] = hex2u(h3) & e3;
            }
        }

        // ---- rowsum MMAs (B = ones) ----
#pragma unroll
        for (int ks = 0; ks < 4; ks++) {
            mma_f16(accR[0], pa[0][ks][0], pa[1][ks][0], pa[0][ks][1], pa[1][ks][1],
                    BONES, BONES);
            mma_f16(accR[1], pa[2][ks][0], pa[3][ks][0], pa[2][ks][1], pa[3][ks][1],
                    BONES, BONES);
        }

        // ---- phase B: fp16 tensor-core PV ----
        const uint4* tile4 = (const uint4*)&WhT_s[cur][0];
        int c0 = tig ^ sg;
#pragma unroll
        for (int dt = 0; dt < 8; dt++) {
            int rowq = (8 * dt + gid) * 8;
            uint4 v0 = tile4[rowq + c0];
            uint4 v1 = tile4[rowq + (c0 ^ 4)];
            unsigned int bw0[4], bw1[4];
            *(uint4*)bw0 = v0;
            *(uint4*)bw1 = v1;
#pragma unroll
            for (int ks = 0; ks < 4; ks++) {
                mma_f16(accA[dt], pa[0][ks][0], pa[1][ks][0], pa[0][ks][1], pa[1][ks][1],
                        bw0[ks], bw1[ks]);
                mma_f16(accB[dt], pa[2][ks][0], pa[3][ks][0], pa[2][ks][1], pa[3][ks][1],
                        bw0[ks], bw1[ks]);
            }
        }
    }

    // rowsums come straight out of accR (cols 0/2 hold rows rr and rr+1)
    float rsv[4] = {accR[0][0], accR[0][2], accR[1][0], accR[1][2]};
    float inv[4];
#pragma unroll
    for (int rr = 0; rr < 4; rr++) inv[rr] = rsv[rr] > 0.f ? 1.f / rsv[rr] : 0.f;

#pragma unroll
    for (int rr = 0; rr < 4; rr++) {
        float* o = g_hnew + (size_t)(b * Nn + i0 + ibase + 8 * rr) * C + hh * Dn;
        float (*ac)[4] = (rr < 2) ? accA : accB;
        int sel = 2 * (rr & 1);
#pragma unroll
        for (int dt = 0; dt < 8; dt++) {
            int d = 8 * dt + 2 * tig;
            *(float2*)&o[d] = make_float2(ac[dt][sel] * inv[rr], ac[dt][sel + 1] * inv[rr]);
        }
    }
}

// ============================================================
// K4/K5: BatchNorm stats (deterministic two-stage)
// ============================================================
__global__ __launch_bounds__(256) void k_bn_partial() {
    int c = threadIdx.x;
    int r0 = blockIdx.x * 32;
    float s = 0.f, ss = 0.f;
#pragma unroll 8
    for (int r = 0; r < 32; r++) {
        float x = g_hnew[(size_t)(r0 + r) * C + c];
        s += x; ss += x * x;
    }
    g_psum[blockIdx.x * C + c] = s;
    g_psq [blockIdx.x * C + c] = ss;
}

__global__ __launch_bounds__(256) void k_bn_final() {
    int c = threadIdx.x;
    float s = 0.f, ss = 0.f;
#pragma unroll 8
    for (int k = 0; k < 256; k++) {
        s  += g_psum[k * C + c];
        ss += g_psq [k * C + c];
    }
    float m = s * (1.f / (float)ROWS);
    float v = ss * (1.f / (float)ROWS) - m * m;
    v = v > 0.f ? v : 0.f;
    g_mean[c] = m;
    g_rstd[c] = rsqrtf(v + 1e-5f);
}

// ============================================================
// K6: normalize + affine + ELU
// ============================================================
__global__ __launch_bounds__(256) void k_norm(const float* __restrict__ gamma,
                                              const float* __restrict__ beta,
                                              float* __restrict__ out) {
    int idx = blockIdx.x * 256 + threadIdx.x;
    int c = (idx & 63) * 4;
    float4 x = ((const float4*)g_hnew)[idx];
    float4 y;
    y.x = (x.x - g_mean[c + 0]) * g_rstd[c + 0] * gamma[c + 0] + beta[c + 0];
    y.y = (x.y - g_mean[c + 1]) * g_rstd[c + 1] * gamma[c + 1] + beta[c + 1];
    y.z = (x.z - g_mean[c + 2]) * g_rstd[c + 2] * gamma[c + 2] + beta[c + 2];
    y.w = (x.w - g_mean[c + 3]) * g_rstd[c + 3] * gamma[c + 3] + beta[c + 3];
    y.x = y.x > 0.f ? y.x : expm1f(y.x);
    y.y = y.y > 0.f ? y.y : expm1f(y.y);
    y.z = y.z > 0.f ? y.z : expm1f(y.z);
    y.w = y.w > 0.f ? y.w : expm1f(y.w);
    ((float4*)out)[idx] = y;
}

// ============================================================
extern "C" void kernel_launch(void* const* d_in, const int* in_sizes, int n_in,
                              void* d_out, int out_size) {
    const float* h     = (const float*)d_in[0];
    const float* W     = (const float*)d_in[1];
    const float* a     = (const float*)d_in[2];
    const float* gamma = (const float*)d_in[3];
    const float* beta  = (const float*)d_in[4];
    const int*   adj   = (const int*)d_in[5];
    float* out = (float*)d_out;

    k_gemm<<<ROWS / 32, 256>>>(h, W);
    k_srcdst<<<Bn * Nn * Hn / 8, 256>>>(a);
    k_maskexp<<<Nn * Nn / 16 / 256, 256>>>(adj);
    dim3 g(Nn / 128, Hn, Bn);      // 16 x 4 x 4 = 256 blocks, launch #4 for ncu
    k_attn<<<g, 128>>>();
    k_bn_partial<<<256, 256>>>();
    k_bn_final<<<1, 256>>>();
    k_norm<<<ROWS * C / 4 / 256, 256>>>(gamma, beta, out);
}

// round 15
// speedup vs baseline: 1.3158x; 1.0980x over previous
#include <cuda_runtime.h>
#include <cuda_fp16.h>
#include <math.h>

#define Bn 4
#define Nn 2048
#define IND 128
#define Hn 4
#define Dn 64
#define C 256   // H*D
#define ROWS (Bn*Nn)   // 8192
#define LOG2E 1.4426950408889634f

// ---- scratch (static device globals; no allocation) ----
__device__ float g_Wh[ROWS*C];                    // [B*N, 256] fp32
__device__ unsigned int g_WhT[Bn*Hn*Dn*Nn/2];     // fp16 pairs, [b][h][d][n]
__device__ unsigned char g_maskp[(size_t)Nn*Nn];  // permuted byte masks (fragment order)
__device__ float g_src[Bn*Hn*Nn];                 // pre-scaled by LOG2E (fp32)
__device__ unsigned short g_dsth[Bn*Hn*Nn];       // pre-scaled by LOG2E (fp16)
__device__ float g_hnew[ROWS*C];
__device__ float g_psum[256*C];
__device__ float g_psq[256*C];
__device__ float g_mean[C];
__device__ float g_rstd[C];

__device__ __forceinline__ unsigned int packh2(float a, float b) {
    __half2 h = __floats2half2_rn(a, b);   // low = a, high = b
    return *(unsigned int*)&h;
}
__device__ __forceinline__ unsigned int hadd2u(unsigned int a, unsigned int b) {
    unsigned int r;
    asm("add.f16x2 %0, %1, %2;" : "=r"(r) : "r"(a), "r"(b));
    return r;
}
__device__ __forceinline__ unsigned int hmul2u(unsigned int a, unsigned int b) {
    unsigned int r;
    asm("mul.f16x2 %0, %1, %2;" : "=r"(r) : "r"(a), "r"(b));
    return r;
}
__device__ __forceinline__ unsigned int hmax2u(unsigned int a, unsigned int b) {
    unsigned int r;
    asm("max.f16x2 %0, %1, %2;" : "=r"(r) : "r"(a), "r"(b));
    return r;
}
__device__ __forceinline__ unsigned int hex2u(unsigned int a) {
    unsigned int r;
    asm("ex2.approx.f16x2 %0, %1;" : "=r"(r) : "r"(a));
    return r;
}
__device__ __forceinline__ void mma_f16(float* c,
                                        unsigned int a0, unsigned int a1,
                                        unsigned int a2, unsigned int a3,
                                        unsigned int b0, unsigned int b1) {
    asm("mma.sync.aligned.m16n8k16.row.col.f32.f16.f16.f32 "
        "{%0,%1,%2,%3}, {%4,%5,%6,%7}, {%8,%9}, {%0,%1,%2,%3};"
        : "+f"(c[0]), "+f"(c[1]), "+f"(c[2]), "+f"(c[3])
        : "r"(a0), "r"(a1), "r"(a2), "r"(a3), "r"(b0), "r"(b1));
}
__device__ __forceinline__ void cp16(unsigned int saddr, const void* gptr) {
    asm volatile("cp.async.cg.shared.global [%0], [%1], 16;" :: "r"(saddr), "l"(gptr));
}
__device__ __forceinline__ int sigma3(int g) {   // chunk-swizzle: {0,4,1,5,2,6,3,7}
    return ((g & 1) << 2) | (g >> 1);
}

// ============================================================
// K1: Wh = h @ W ; also emit transposed fp16 copy g_WhT[b][h][d][n]
// ============================================================
__global__ __launch_bounds__(256) void k_gemm(const float* __restrict__ hIn,
                                              const float* __restrict__ W) {
    __shared__ float hs[32 * IND];
    int row0 = blockIdx.x * 32;
    const float4* gp = (const float4*)(hIn + (size_t)row0 * IND);
    float4* sp = (float4*)hs;
    for (int i = threadIdx.x; i < 32 * IND / 4; i += 256) sp[i] = gp[i];
    __syncthreads();

    int c = threadIdx.x;
    float acc[32];
#pragma unroll
    for (int r = 0; r < 32; r++) acc[r] = 0.f;

    for (int k = 0; k < IND; k += 4) {
        float w0 = __ldg(&W[(k + 0) * C + c]);
        float w1 = __ldg(&W[(k + 1) * C + c]);
        float w2 = __ldg(&W[(k + 2) * C + c]);
        float w3 = __ldg(&W[(k + 3) * C + c]);
#pragma unroll
        for (int r = 0; r < 32; r++) {
            float4 hv = *(const float4*)&hs[r * IND + k];
            acc[r] += hv.x * w0 + hv.y * w1 + hv.z * w2 + hv.w * w3;
        }
    }
#pragma unroll
    for (int r = 0; r < 32; r++) g_Wh[(size_t)(row0 + r) * C + c] = acc[r];

    // transposed fp16 copy (rows stay inside one b: 2048 % 32 == 0)
    int b = row0 >> 11;
    int n0 = row0 & (Nn - 1);
    int hh = c >> 6, d = c & 63;
    unsigned int* wt = g_WhT + ((size_t)(((b * Hn + hh) * Dn + d)) * Nn + n0) / 2;
    unsigned int wbuf[16];
#pragma unroll
    for (int m = 0; m < 16; m++) wbuf[m] = packh2(acc[2 * m], acc[2 * m + 1]);
#pragma unroll
    for (int q = 0; q < 4; q++) ((uint4*)wt)[q] = ((uint4*)wbuf)[q];
}

// ============================================================
// K2: src/dst projections (pre-scaled by LOG2E). One warp per (b,n,h).
// ============================================================
__global__ __launch_bounds__(256) void k_srcdst(const float* __restrict__ a) {
    int gw = blockIdx.x * 8 + (threadIdx.x >> 5);
    int lane = threadIdx.x & 31;
    int hh = gw & 3;
    int n  = (gw >> 2) & (Nn - 1);
    int b  = gw >> 13;
    const float2 v  = ((const float2*)(g_Wh + (size_t)(b * Nn + n) * C + hh * Dn))[lane];
    const float2 a1 = ((const float2*)(a + hh * 2 * Dn))[lane];
    const float2 a2 = ((const float2*)(a + hh * 2 * Dn + Dn))[lane];
    float s = v.x * a1.x + v.y * a1.y;
    float d = v.x * a2.x + v.y * a2.y;
#pragma unroll
    for (int o = 16; o > 0; o >>= 1) {
        s += __shfl_xor_sync(0xffffffffu, s, o);
        d += __shfl_xor_sync(0xffffffffu, d, o);
    }
    if (lane == 0) {
        int idx = (b * Hn + hh) * Nn + n;
        g_src[idx] = s * LOG2E;
        __half hd = __float2half(d * LOG2E);
        g_dsth[idx] = *(unsigned short*)&hd;
    }
}

// ============================================================
// K2b: expand adjacency into PERMUTED byte masks.
// Output layout per row i, tile jt (64 j), thread-slot tig:
//   bytes [jt*64 + 16*tig + 8*v + u] = mask(i, jt*64 + 32*v + 8*tig + u)
// so k_attn reads one LDG.128 per (row, tile).
// ============================================================
__global__ __launch_bounds__(256) void k_maskexp(const int* __restrict__ adj) {
    int t = blockIdx.x * 256 + threadIdx.x;  // 2048*32*4 threads
    int tig = t & 3;
    int jt  = (t >> 2) & 31;
    int i   = t >> 7;
    const int* base = adj + (size_t)i * Nn + jt * 64 + 8 * tig;
    int4 a0 = *(const int4*)(base);
    int4 a1 = *(const int4*)(base + 4);
    int4 b0 = *(const int4*)(base + 32);
    int4 b1 = *(const int4*)(base + 36);
    unsigned int u[4];
    u[0] = (a0.x ? 0xFFu : 0u) | (a0.y ? 0xFF00u : 0u)
         | (a0.z ? 0xFF0000u : 0u) | (a0.w ? 0xFF000000u : 0u);
    u[1] = (a1.x ? 0xFFu : 0u) | (a1.y ? 0xFF00u : 0u)
         | (a1.z ? 0xFF0000u : 0u) | (a1.w ? 0xFF000000u : 0u);
    u[2] = (b0.x ? 0xFFu : 0u) | (b0.y ? 0xFF00u : 0u)
         | (b0.z ? 0xFF0000u : 0u) | (b0.w ? 0xFF000000u : 0u);
    u[3] = (b1.x ? 0xFFu : 0u) | (b1.y ? 0xFF00u : 0u)
         | (b1.z ? 0xFF0000u : 0u) | (b1.w ? 0xFF000000u : 0u);
    *(uint4*)(g_maskp + (size_t)i * Nn + jt * 64 + 16 * tig) = *(uint4*)u;
}

// ============================================================
// K3 helpers
// ============================================================
__device__ __forceinline__ void tile_compute(
    const uint4* mreg, const uint4* dreg,
    const unsigned int* wht_tile, const unsigned int* src2,
    int gid, int tig, int sg,
    float (*accA)[4], float (*accB)[4], float (*accR)[4])
{
    const unsigned int BONES = 0x3C003C00u;   // half2(1.0, 1.0)
    const unsigned int H02   = 0x32663266u;   // half2(0.2, 0.2)
    unsigned int pa[4][4][2];   // [rr][ks][v]
#pragma unroll
    for (int v = 0; v < 2; v++) {
        unsigned int dh[4];
        *(uint4*)dh = dreg[v];
#pragma unroll
        for (int rr = 0; rr < 4; rr++) {
            unsigned int mlo = (v == 0) ? mreg[rr].x : mreg[rr].z;
            unsigned int mhi = (v == 0) ? mreg[rr].y : mreg[rr].w;
            unsigned int e0 = __byte_perm(mlo, 0, 0x1100);
            unsigned int e1 = __byte_perm(mlo, 0, 0x3322);
            unsigned int e2 = __byte_perm(mhi, 0, 0x1100);
            unsigned int e3 = __byte_perm(mhi, 0, 0x3322);
            unsigned int s2 = src2[rr];
            unsigned int h0 = hadd2u(s2, dh[0]);
            unsigned int h1 = hadd2u(s2, dh[1]);
            unsigned int h2 = hadd2u(s2, dh[2]);
            unsigned int h3 = hadd2u(s2, dh[3]);
            h0 = hmax2u(h0, hmul2u(h0, H02));
            h1 = hmax2u(h1, hmul2u(h1, H02));
            h2 = hmax2u(h2, hmul2u(h2, H02));
            h3 = hmax2u(h3, hmul2u(h3, H02));
            pa[rr][0][v] = hex2u(h0) & e0;
            pa[rr][1][v] = hex2u(h1) & e1;
            pa[rr][2][v] = hex2u(h2) & e2;
            pa[rr][3][v] = hex2u(h3) & e3;
        }
    }

    // rowsum MMAs (B = ones)
#pragma unroll
    for (int ks = 0; ks < 4; ks++) {
        mma_f16(accR[0], pa[0][ks][0], pa[1][ks][0], pa[0][ks][1], pa[1][ks][1],
                BONES, BONES);
        mma_f16(accR[1], pa[2][ks][0], pa[3][ks][0], pa[2][ks][1], pa[3][ks][1],
                BONES, BONES);
    }

    // PV MMAs
    const uint4* tile4 = (const uint4*)wht_tile;
    int c0 = tig ^ sg;
#pragma unroll
    for (int dt = 0; dt < 8; dt++) {
        int rowq = (8 * dt + gid) * 8;
        uint4 v0 = tile4[rowq + c0];
        uint4 v1 = tile4[rowq + (c0 ^ 4)];
        unsigned int bw0[4], bw1[4];
        *(uint4*)bw0 = v0;
        *(uint4*)bw1 = v1;
#pragma unroll
        for (int ks = 0; ks < 4; ks++) {
            mma_f16(accA[dt], pa[0][ks][0], pa[1][ks][0], pa[0][ks][1], pa[1][ks][1],
                    bw0[ks], bw1[ks]);
            mma_f16(accB[dt], pa[2][ks][0], pa[3][ks][0], pa[2][ks][1], pa[3][ks][1],
                    bw0[ks], bw1[ks]);
        }
    }
}

// ============================================================
// K3: attention. 256 blocks x 128 thr. CTA tile 128 i x 64 d.
// 4 warps, each m32 x 64d, fp16 mma.m16n8k16, f16x2 phase A.
// Only WhT in smem (cp.async double-buffer). Mask/dst via
// coalesced LDG.128 prefetched one tile ahead into registers.
// ============================================================
__global__ __launch_bounds__(128, 2) void k_attn() {
    __shared__ unsigned int WhT_s[2][64 * 32];       // fp16 pairs: [d][j/2], 8 KB each

    int b  = blockIdx.z, hh = blockIdx.y;
    int i0 = blockIdx.x * 128;
    int t  = threadIdx.x;
    int w  = t >> 5, lane = t & 31;
    int gid = lane >> 2, tig = lane & 3;
    int sg = sigma3(gid);

    int ibase = 32 * w + gid;
    const float* sbp = g_src + (b * Hn + hh) * Nn + i0;
    unsigned int src2[4];
#pragma unroll
    for (int rr = 0; rr < 4; rr++) {
        float sv = sbp[ibase + 8 * rr];
        src2[rr] = packh2(sv, sv);
    }

    float accA[8][4], accB[8][4], accR[2][4];
#pragma unroll
    for (int dt = 0; dt < 8; dt++)
#pragma unroll
        for (int r = 0; r < 4; r++) { accA[dt][r] = 0.f; accB[dt][r] = 0.f; }
#pragma unroll
    for (int r = 0; r < 4; r++) { accR[0][r] = 0.f; accR[1][r] = 0.f; }

    const unsigned int* WhTg = g_WhT + (size_t)((b * Hn + hh) * Dn) * (Nn / 2);
    const unsigned int* dstp = (const unsigned int*)g_dsth + (b * Hn + hh) * (Nn / 2);

    // per-rr mask row pointers (permuted layout)
    const unsigned char* mrowp[4];
#pragma unroll
    for (int rr = 0; rr < 4; rr++)
        mrowp[rr] = g_maskp + (size_t)(i0 + ibase + 8 * rr) * Nn + 16 * tig;

    // Wh staging mapping: row d_l = t>>1, chunk-quad c2 = t&1
    int d_l = t >> 1, c2 = t & 1;
    int sgs = sigma3(d_l & 7);
    unsigned int whbase = (unsigned int)__cvta_generic_to_shared(&WhT_s[0][0]);
    const unsigned int WHSTRIDE = 64 * 32 * 4;       // 8 KB

    uint4 mA[4], mB[4], dA[2], dB[2];

    // ---- prologue: regs for tile 0, stage WhT tile 0 into buf 0 ----
#pragma unroll
    for (int rr = 0; rr < 4; rr++) mA[rr] = __ldg((const uint4*)(mrowp[rr]));
    dA[0] = __ldg((const uint4*)(dstp + 4 * tig));
    dA[1] = __ldg((const uint4*)(dstp + 16 + 4 * tig));
    {
        const unsigned int* gsrc = WhTg + (size_t)d_l * (Nn / 2);
        unsigned int srow = whbase + d_l * 128;
#pragma unroll
        for (int u = 0; u < 4; u++) {
            int ch = 4 * c2 + u;
            cp16(srow + 16 * (ch ^ sgs), gsrc + 4 * ch);
        }
        asm volatile("cp.async.commit_group;");
    }

    for (int jt2 = 0; jt2 < 16; jt2++) {
        int jtA = 2 * jt2;
        // ---------- tile A: buffer 0, register set A ----------
        asm volatile("cp.async.wait_group 0;");
        __syncthreads();
        {
            int jn = jtA + 1;   // always < 32
            const unsigned int* gsrc = WhTg + (size_t)d_l * (Nn / 2) + jn * 32;
            unsigned int srow = whbase + WHSTRIDE + d_l * 128;
#pragma unroll
            for (int u = 0; u < 4; u++) {
                int ch = 4 * c2 + u;
                cp16(srow + 16 * (ch ^ sgs), gsrc + 4 * ch);
            }
            asm volatile("cp.async.commit_group;");
#pragma unroll
            for (int rr = 0; rr < 4; rr++)
                mB[rr] = __ldg((const uint4*)(mrowp[rr] + jn * 64));
            dB[0] = __ldg((const uint4*)(dstp + jn * 32 + 4 * tig));
            dB[1] = __ldg((const uint4*)(dstp + jn * 32 + 16 + 4 * tig));
        }
        tile_compute(mA, dA, &WhT_s[0][0], src2, gid, tig, sg, accA, accB, accR);

        // ---------- tile B: buffer 1, register set B ----------
        asm volatile("cp.async.wait_group 0;");
        __syncthreads();
        if (jtA + 2 < 32) {
            int jn = jtA + 2;
            const unsigned int* gsrc = WhTg + (size_t)d_l * (Nn / 2) + jn * 32;
            unsigned int srow = whbase + d_l * 128;
#pragma unroll
            for (int u = 0; u < 4; u++) {
                int ch = 4 * c2 + u;
                cp16(srow + 16 * (ch ^ sgs), gsrc + 4 * ch);
            }
            asm volatile("cp.async.commit_group;");
#pragma unroll
            for (int rr = 0; rr < 4; rr++)
                mA[rr] = __ldg((const uint4*)(mrowp[rr] + jn * 64));
            dA[0] = __ldg((const uint4*)(dstp + jn * 32 + 4 * tig));
            dA[1] = __ldg((const uint4*)(dstp + jn * 32 + 16 + 4 * tig));
        }
        tile_compute(mB, dB, &WhT_s[1][0], src2, gid, tig, sg, accA, accB, accR);
    }

    // rowsums from accR (cols 0/2 hold rows rr and rr+1)
    float rsv[4] = {accR[0][0], accR[0][2], accR[1][0], accR[1][2]};
    float inv[4];
#pragma unroll
    for (int rr = 0; rr < 4; rr++) inv[rr] = rsv[rr] > 0.f ? 1.f / rsv[rr] : 0.f;

#pragma unroll
    for (int rr = 0; rr < 4; rr++) {
        float* o = g_hnew + (size_t)(b * Nn + i0 + ibase + 8 * rr) * C + hh * Dn;
        float (*ac)[4] = (rr < 2) ? accA : accB;
        int sel = 2 * (rr & 1);
#pragma unroll
        for (int dt = 0; dt < 8; dt++) {
            int d = 8 * dt + 2 * tig;
            *(float2*)&o[d] = make_float2(ac[dt][sel] * inv[rr], ac[dt][sel + 1] * inv[rr]);
        }
    }
}

// ============================================================
// K4/K5: BatchNorm stats (deterministic two-stage)
// ============================================================
__global__ __launch_bounds__(256) void k_bn_partial() {
    int c = threadIdx.x;
    int r0 = blockIdx.x * 32;
    float s = 0.f, ss = 0.f;
#pragma unroll 8
    for (int r = 0; r < 32; r++) {
        float x = g_hnew[(size_t)(r0 + r) * C + c];
        s += x; ss += x * x;
    }
    g_psum[blockIdx.x * C + c] = s;
    g_psq [blockIdx.x * C + c] = ss;
}

__global__ __launch_bounds__(256) void k_bn_final() {
    int c = threadIdx.x;
    float s = 0.f, ss = 0.f;
#pragma unroll 8
    for (int k = 0; k < 256; k++) {
        s  += g_psum[k * C + c];
        ss += g_psq [k * C + c];
    }
    float m = s * (1.f / (float)ROWS);
    float v = ss * (1.f / (float)ROWS) - m * m;
    v = v > 0.f ? v : 0.f;
    g_mean[c] = m;
    g_rstd[c] = rsqrtf(v + 1e-5f);
}

// ============================================================
// K6: normalize + affine + ELU
// ============================================================
__global__ __launch_bounds__(256) void k_norm(const float* __restrict__ gamma,
                                              const float* __restrict__ beta,
                                              float* __restrict__ out) {
    int idx = blockIdx.x * 256 + threadIdx.x;
    int c = (idx & 63) * 4;
    float4 x = ((const float4*)g_hnew)[idx];
    float4 y;
    y.x = (x.x - g_mean[c + 0]) * g_rstd[c + 0] * gamma[c + 0] + beta[c + 0];
    y.y = (x.y - g_mean[c + 1]) * g_rstd[c + 1] * gamma[c + 1] + beta[c + 1];
    y.z = (x.z - g_mean[c + 2]) * g_rstd[c + 2] * gamma[c + 2] + beta[c + 2];
    y.w = (x.w - g_mean[c + 3]) * g_rstd[c + 3] * gamma[c + 3] + beta[c + 3];
    y.x = y.x > 0.f ? y.x : expm1f(y.x);
    y.y = y.y > 0.f ? y.y : expm1f(y.y);
    y.z = y.z > 0.f ? y.z : expm1f(y.z);
    y.w = y.w > 0.f ? y.w : expm1f(y.w);
    ((float4*)out)[idx] = y;
}

// ============================================================
extern "C" void kernel_launch(void* const* d_in, const int* in_sizes, int n_in,
                              void* d_out, int out_size) {
    const float* h     = (const float*)d_in[0];
    const float* W     = (const float*)d_in[1];
    const float* a     = (const float*)d_in[2];
    const float* gamma = (const float*)d_in[3];
    const float* beta  = (const float*)d_in[4];
    const int*   adj   = (const int*)d_in[5];
    float* out = (float*)d_out;

    k_gemm<<<ROWS / 32, 256>>>(h, W);
    k_srcdst<<<Bn * Nn * Hn / 8, 256>>>(a);
    k_maskexp<<<Nn * 32 * 4 / 256, 256>>>(adj);
    dim3 g(Nn / 128, Hn, Bn);      // 16 x 4 x 4 = 256 blocks, launch #4 for ncu
    k_attn<<<g, 128>>>();
    k_bn_partial<<<256, 256>>>();
    k_bn_final<<<1, 256>>>();
    k_norm<<<ROWS * C / 4 / 256, 256>>>(gamma, beta, out);
}

// round 16
// speedup vs baseline: 1.3421x; 1.0200x over previous
#include <cuda_runtime.h>
#include <cuda_fp16.h>
#include <math.h>

#define Bn 4
#define Nn 2048
#define IND 128
#define Hn 4
#define Dn 64
#define C 256   // H*D
#define ROWS (Bn*Nn)   // 8192
#define LOG2E 1.4426950408889634f

// ---- scratch (static device globals; no allocation) ----
__device__ float g_Wh[ROWS*C];                    // [B*N, 256] fp32
__device__ unsigned int g_WhT[Bn*Hn*Dn*Nn/2];     // fp16 pairs, [b][h][d][n]
__device__ unsigned char g_maskp[(size_t)Nn*Nn];  // permuted byte masks (fragment order)
__device__ unsigned short g_esh[Bn*Hn*Nn];        // 2^(src*log2e)        fp16
__device__ unsigned short g_fsh[Bn*Hn*Nn];        // 2^(0.2*src*log2e)    fp16
__device__ unsigned short g_edh[Bn*Hn*Nn];        // 2^(dst*log2e)        fp16
__device__ unsigned short g_fdh[Bn*Hn*Nn];        // 2^(0.2*dst*log2e)    fp16
__device__ float g_hnew[ROWS*C];
__device__ float g_psum[256*C];
__device__ float g_psq[256*C];
__device__ float g_mean[C];
__device__ float g_rstd[C];

__device__ __forceinline__ unsigned int packh2(float a, float b) {
    __half2 h = __floats2half2_rn(a, b);   // low = a, high = b
    return *(unsigned int*)&h;
}
__device__ __forceinline__ unsigned int hmul2u(unsigned int a, unsigned int b) {
    unsigned int r;
    asm("mul.f16x2 %0, %1, %2;" : "=r"(r) : "r"(a), "r"(b));
    return r;
}
// per-half mask: 0xFFFF where a >= b
__device__ __forceinline__ unsigned int hge2mask(unsigned int a, unsigned int b) {
    unsigned int r;
    asm("set.ge.u32.f16x2 %0, %1, %2;" : "=r"(r) : "r"(a), "r"(b));
    return r;
}
__device__ __forceinline__ void mma_f16(float* c,
                                        unsigned int a0, unsigned int a1,
                                        unsigned int a2, unsigned int a3,
                                        unsigned int b0, unsigned int b1) {
    asm("mma.sync.aligned.m16n8k16.row.col.f32.f16.f16.f32 "
        "{%0,%1,%2,%3}, {%4,%5,%6,%7}, {%8,%9}, {%0,%1,%2,%3};"
        : "+f"(c[0]), "+f"(c[1]), "+f"(c[2]), "+f"(c[3])
        : "r"(a0), "r"(a1), "r"(a2), "r"(a3), "r"(b0), "r"(b1));
}
__device__ __forceinline__ void cp16(unsigned int saddr, const void* gptr) {
    asm volatile("cp.async.cg.shared.global [%0], [%1], 16;" :: "r"(saddr), "l"(gptr));
}
__device__ __forceinline__ int sigma3(int g) {   // chunk-swizzle: {0,4,1,5,2,6,3,7}
    return ((g & 1) << 2) | (g >> 1);
}

// ============================================================
// K1: Wh = h @ W ; also emit transposed fp16 copy g_WhT[b][h][d][n]
// ============================================================
__global__ __launch_bounds__(256) void k_gemm(const float* __restrict__ hIn,
                                              const float* __restrict__ W) {
    __shared__ float hs[32 * IND];
    int row0 = blockIdx.x * 32;
    const float4* gp = (const float4*)(hIn + (size_t)row0 * IND);
    float4* sp = (float4*)hs;
    for (int i = threadIdx.x; i < 32 * IND / 4; i += 256) sp[i] = gp[i];
    __syncthreads();

    int c = threadIdx.x;
    float acc[32];
#pragma unroll
    for (int r = 0; r < 32; r++) acc[r] = 0.f;

    for (int k = 0; k < IND; k += 4) {
        float w0 = __ldg(&W[(k + 0) * C + c]);
        float w1 = __ldg(&W[(k + 1) * C + c]);
        float w2 = __ldg(&W[(k + 2) * C + c]);
        float w3 = __ldg(&W[(k + 3) * C + c]);
#pragma unroll
        for (int r = 0; r < 32; r++) {
            float4 hv = *(const float4*)&hs[r * IND + k];
            acc[r] += hv.x * w0 + hv.y * w1 + hv.z * w2 + hv.w * w3;
        }
    }
#pragma unroll
    for (int r = 0; r < 32; r++) g_Wh[(size_t)(row0 + r) * C + c] = acc[r];

    // transposed fp16 copy (rows stay inside one b: 2048 % 32 == 0)
    int b = row0 >> 11;
    int n0 = row0 & (Nn - 1);
    int hh = c >> 6, d = c & 63;
    unsigned int* wt = g_WhT + ((size_t)(((b * Hn + hh) * Dn + d)) * Nn + n0) / 2;
    unsigned int wbuf[16];
#pragma unroll
    for (int m = 0; m < 16; m++) wbuf[m] = packh2(acc[2 * m], acc[2 * m + 1]);
#pragma unroll
    for (int q = 0; q < 4; q++) ((uint4*)wt)[q] = ((uint4*)wbuf)[q];
}

// ============================================================
// K2: src/dst projections -> factorized exponentials (fp16).
// Es=2^(s*log2e), Fs=2^(0.2*s*log2e); Ed,Fd likewise for dst.
// exp(leaky(s+d)) == (Es*Ed >= 1) ? Es*Ed : Fs*Fd.
// ============================================================
__global__ __launch_bounds__(256) void k_srcdst(const float* __restrict__ a) {
    int gw = blockIdx.x * 8 + (threadIdx.x >> 5);
    int lane = threadIdx.x & 31;
    int hh = gw & 3;
    int n  = (gw >> 2) & (Nn - 1);
    int b  = gw >> 13;
    const float2 v  = ((const float2*)(g_Wh + (size_t)(b * Nn + n) * C + hh * Dn))[lane];
    const float2 a1 = ((const float2*)(a + hh * 2 * Dn))[lane];
    const float2 a2 = ((const float2*)(a + hh * 2 * Dn + Dn))[lane];
    float s = v.x * a1.x + v.y * a1.y;
    float d = v.x * a2.x + v.y * a2.y;
#pragma unroll
    for (int o = 16; o > 0; o >>= 1) {
        s += __shfl_xor_sync(0xffffffffu, s, o);
        d += __shfl_xor_sync(0xffffffffu, d, o);
    }
    if (lane == 0) {
        int idx = (b * Hn + hh) * Nn + n;
        float sl = s * LOG2E, dl = d * LOG2E;
        __half es = __float2half(exp2f(sl));
        __half fs = __float2half(exp2f(0.2f * sl));
        __half ed = __float2half(exp2f(dl));
        __half fd = __float2half(exp2f(0.2f * dl));
        g_esh[idx] = *(unsigned short*)&es;
        g_fsh[idx] = *(unsigned short*)&fs;
        g_edh[idx] = *(unsigned short*)&ed;
        g_fdh[idx] = *(unsigned short*)&fd;
    }
}

// ============================================================
// K2b: expand adjacency into PERMUTED byte masks.
// bytes [i*Nn + jt*64 + 16*tig + 8*v + u] = mask(i, jt*64 + 32*v + 8*tig + u)
// ============================================================
__global__ __launch_bounds__(256) void k_maskexp(const int* __restrict__ adj) {
    int t = blockIdx.x * 256 + threadIdx.x;  // 2048*32*4 threads
    int tig = t & 3;
    int jt  = (t >> 2) & 31;
    int i   = t >> 7;
    const int* base = adj + (size_t)i * Nn + jt * 64 + 8 * tig;
    int4 a0 = *(const int4*)(base);
    int4 a1 = *(const int4*)(base + 4);
    int4 b0 = *(const int4*)(base + 32);
    int4 b1 = *(const int4*)(base + 36);
    unsigned int u[4];
    u[0] = (a0.x ? 0xFFu : 0u) | (a0.y ? 0xFF00u : 0u)
         | (a0.z ? 0xFF0000u : 0u) | (a0.w ? 0xFF000000u : 0u);
    u[1] = (a1.x ? 0xFFu : 0u) | (a1.y ? 0xFF00u : 0u)
         | (a1.z ? 0xFF0000u : 0u) | (a1.w ? 0xFF000000u : 0u);
    u[2] = (b0.x ? 0xFFu : 0u) | (b0.y ? 0xFF00u : 0u)
         | (b0.z ? 0xFF0000u : 0u) | (b0.w ? 0xFF000000u : 0u);
    u[3] = (b1.x ? 0xFFu : 0u) | (b1.y ? 0xFF00u : 0u)
         | (b1.z ? 0xFF0000u : 0u) | (b1.w ? 0xFF000000u : 0u);
    *(uint4*)(g_maskp + (size_t)i * Nn + jt * 64 + 16 * tig) = *(uint4*)u;
}

// ============================================================
// K3 tile compute: factorized P (no MUFU) + rowsum/PV MMAs
// ============================================================
__device__ __forceinline__ void tile_compute(
    const uint4* mreg, const uint4* edreg, const uint4* fdreg,
    const unsigned int* wht_tile,
    const unsigned int* es2, const unsigned int* fs2,
    int gid, int tig, int sg,
    float (*accA)[4], float (*accB)[4], float (*accR)[4])
{
    const unsigned int BONES = 0x3C003C00u;   // half2(1.0, 1.0)
    unsigned int pa[4][4][2];   // [rr][ks][v]
#pragma unroll
    for (int v = 0; v < 2; v++) {
        unsigned int edh[4], fdh[4];
        *(uint4*)edh = edreg[v];
        *(uint4*)fdh = fdreg[v];
#pragma unroll
        for (int rr = 0; rr < 4; rr++) {
            unsigned int mlo = (v == 0) ? mreg[rr].x : mreg[rr].z;
            unsigned int mhi = (v == 0) ? mreg[rr].y : mreg[rr].w;
            unsigned int e0 = __byte_perm(mlo, 0, 0x1100);
            unsigned int e1 = __byte_perm(mlo, 0, 0x3322);
            unsigned int e2 = __byte_perm(mhi, 0, 0x1100);
            unsigned int e3 = __byte_perm(mhi, 0, 0x3322);
            unsigned int es = es2[rr], fs = fs2[rr];
#pragma unroll
            for (int ks = 0; ks < 4; ks++) {
                unsigned int m1 = hmul2u(es, edh[ks]);
                unsigned int m2 = hmul2u(fs, fdh[ks]);
                unsigned int ge = hge2mask(m1, BONES);
                unsigned int sel = (m1 & ge) | (m2 & ~ge);
                unsigned int ek = (ks == 0) ? e0 : (ks == 1) ? e1 : (ks == 2) ? e2 : e3;
                pa[rr][ks][v] = sel & ek;
            }
        }
    }

    // rowsum MMAs (B = ones)
#pragma unroll
    for (int ks = 0; ks < 4; ks++) {
        mma_f16(accR[0], pa[0][ks][0], pa[1][ks][0], pa[0][ks][1], pa[1][ks][1],
                BONES, BONES);
        mma_f16(accR[1], pa[2][ks][0], pa[3][ks][0], pa[2][ks][1], pa[3][ks][1],
                BONES, BONES);
    }

    // PV MMAs
    const uint4* tile4 = (const uint4*)wht_tile;
    int c0 = tig ^ sg;
#pragma unroll
    for (int dt = 0; dt < 8; dt++) {
        int rowq = (8 * dt + gid) * 8;
        uint4 v0 = tile4[rowq + c0];
        uint4 v1 = tile4[rowq + (c0 ^ 4)];
        unsigned int bw0[4], bw1[4];
        *(uint4*)bw0 = v0;
        *(uint4*)bw1 = v1;
#pragma unroll
        for (int ks = 0; ks < 4; ks++) {
            mma_f16(accA[dt], pa[0][ks][0], pa[1][ks][0], pa[0][ks][1], pa[1][ks][1],
                    bw0[ks], bw1[ks]);
            mma_f16(accB[dt], pa[2][ks][0], pa[3][ks][0], pa[2][ks][1], pa[3][ks][1],
                    bw0[ks], bw1[ks]);
        }
    }
}

// ============================================================
// K3: attention. 256 blocks x 128 thr. CTA tile 128 i x 64 d.
// 4 warps, each m32 x 64d, fp16 mma.m16n8k16.
// Factorized P: NO exp in the hot loop (2 hmul + select per half2).
// WhT in smem (cp.async double-buffer); mask/Ed/Fd via LDG.128
// prefetched one tile ahead into registers.
// ============================================================
__global__ __launch_bounds__(128, 2) void k_attn() {
    __shared__ unsigned int WhT_s[2][64 * 32];       // fp16 pairs: [d][j/2], 8 KB each

    int b  = blockIdx.z, hh = blockIdx.y;
    int i0 = blockIdx.x * 128;
    int t  = threadIdx.x;
    int w  = t >> 5, lane = t & 31;
    int gid = lane >> 2, tig = lane & 3;
    int sg = sigma3(gid);

    int ibase = 32 * w + gid;
    const unsigned short* esp = g_esh + (b * Hn + hh) * Nn + i0;
    const unsigned short* fsp = g_fsh + (b * Hn + hh) * Nn + i0;
    unsigned int es2[4], fs2[4];
#pragma unroll
    for (int rr = 0; rr < 4; rr++) {
        unsigned int e = esp[ibase + 8 * rr];
        unsigned int f = fsp[ibase + 8 * rr];
        es2[rr] = e | (e << 16);
        fs2[rr] = f | (f << 16);
    }

    float accA[8][4], accB[8][4], accR[2][4];
#pragma unroll
    for (int dt = 0; dt < 8; dt++)
#pragma unroll
        for (int r = 0; r < 4; r++) { accA[dt][r] = 0.f; accB[dt][r] = 0.f; }
#pragma unroll
    for (int r = 0; r < 4; r++) { accR[0][r] = 0.f; accR[1][r] = 0.f; }

    const unsigned int* WhTg = g_WhT + (size_t)((b * Hn + hh) * Dn) * (Nn / 2);
    const unsigned int* edp = (const unsigned int*)g_edh + (b * Hn + hh) * (Nn / 2);
    const unsigned int* fdp = (const unsigned int*)g_fdh + (b * Hn + hh) * (Nn / 2);

    const unsigned char* mrowp[4];
#pragma unroll
    for (int rr = 0; rr < 4; rr++)
        mrowp[rr] = g_maskp + (size_t)(i0 + ibase + 8 * rr) * Nn + 16 * tig;

    int d_l = t >> 1, c2 = t & 1;
    int sgs = sigma3(d_l & 7);
    unsigned int whbase = (unsigned int)__cvta_generic_to_shared(&WhT_s[0][0]);
    const unsigned int WHSTRIDE = 64 * 32 * 4;       // 8 KB

    uint4 mA[4], mB[4], eA[2], eB[2], fA[2], fB[2];

    // ---- prologue: regs for tile 0, stage WhT tile 0 into buf 0 ----
#pragma unroll
    for (int rr = 0; rr < 4; rr++) mA[rr] = __ldg((const uint4*)(mrowp[rr]));
    eA[0] = __ldg((const uint4*)(edp + 4 * tig));
    eA[1] = __ldg((const uint4*)(edp + 16 + 4 * tig));
    fA[0] = __ldg((const uint4*)(fdp + 4 * tig));
    fA[1] = __ldg((const uint4*)(fdp + 16 + 4 * tig));
    {
        const unsigned int* gsrc = WhTg + (size_t)d_l * (Nn / 2);
        unsigned int srow = whbase + d_l * 128;
#pragma unroll
        for (int u = 0; u < 4; u++) {
            int ch = 4 * c2 + u;
            cp16(srow + 16 * (ch ^ sgs), gsrc + 4 * ch);
        }
        asm volatile("cp.async.commit_group;");
    }

    for (int jt2 = 0; jt2 < 16; jt2++) {
        int jtA = 2 * jt2;
        // ---------- tile A: buffer 0, register set A ----------
        asm volatile("cp.async.wait_group 0;");
        __syncthreads();
        {
            int jn = jtA + 1;   // always < 32
            const unsigned int* gsrc = WhTg + (size_t)d_l * (Nn / 2) + jn * 32;
            unsigned int srow = whbase + WHSTRIDE + d_l * 128;
#pragma unroll
            for (int u = 0; u < 4; u++) {
                int ch = 4 * c2 + u;
                cp16(srow + 16 * (ch ^ sgs), gsrc + 4 * ch);
            }
            asm volatile("cp.async.commit_group;");
#pragma unroll
            for (int rr = 0; rr < 4; rr++)
                mB[rr] = __ldg((const uint4*)(mrowp[rr] + jn * 64));
            eB[0] = __ldg((const uint4*)(edp + jn * 32 + 4 * tig));
            eB[1] = __ldg((const uint4*)(edp + jn * 32 + 16 + 4 * tig));
            fB[0] = __ldg((const uint4*)(fdp + jn * 32 + 4 * tig));
            fB[1] = __ldg((const uint4*)(fdp + jn * 32 + 16 + 4 * tig));
        }
        tile_compute(mA, eA, fA, &WhT_s[0][0], es2, fs2, gid, tig, sg, accA, accB, accR);

        // ---------- tile B: buffer 1, register set B ----------
        asm volatile("cp.async.wait_group 0;");
        __syncthreads();
        if (jtA + 2 < 32) {
            int jn = jtA + 2;
            const unsigned int* gsrc = WhTg + (size_t)d_l * (Nn / 2) + jn * 32;
            unsigned int srow = whbase + d_l * 128;
#pragma unroll
            for (int u = 0; u < 4; u++) {
                int ch = 4 * c2 + u;
                cp16(srow + 16 * (ch ^ sgs), gsrc + 4 * ch);
            }
            asm volatile("cp.async.commit_group;");
#pragma unroll
            for (int rr = 0; rr < 4; rr++)
                mA[rr] = __ldg((const uint4*)(mrowp[rr] + jn * 64));
            eA[0] = __ldg((const uint4*)(edp + jn * 32 + 4 * tig));
            eA[1] = __ldg((const uint4*)(edp + jn * 32 + 16 + 4 * tig));
            fA[0] = __ldg((const uint4*)(fdp + jn * 32 + 4 * tig));
            fA[1] = __ldg((const uint4*)(fdp + jn * 32 + 16 + 4 * tig));
        }
        tile_compute(mB, eB, fB, &WhT_s[1][0], es2, fs2, gid, tig, sg, accA, accB, accR);
    }

    // rowsums from accR (cols 0/2 hold rows rr and rr+1)
    float rsv[4] = {accR[0][0], accR[0][2], accR[1][0], accR[1][2]};
    float inv[4];
#pragma unroll
    for (int rr = 0; rr < 4; rr++) inv[rr] = rsv[rr] > 0.f ? 1.f / rsv[rr] : 0.f;

#pragma unroll
    for (int rr = 0; rr < 4; rr++) {
        float* o = g_hnew + (size_t)(b * Nn + i0 + ibase + 8 * rr) * C + hh * Dn;
        float (*ac)[4] = (rr < 2) ? accA : accB;
        int sel = 2 * (rr & 1);
#pragma unroll
        for (int dt = 0; dt < 8; dt++) {
            int d = 8 * dt + 2 * tig;
            *(float2*)&o[d] = make_float2(ac[dt][sel] * inv[rr], ac[dt][sel + 1] * inv[rr]);
        }
    }
}

// ============================================================
// K4/K5: BatchNorm stats (deterministic two-stage)
// ============================================================
__global__ __launch_bounds__(256) void k_bn_partial() {
    int c = threadIdx.x;
    int r0 = blockIdx.x * 32;
    float s = 0.f, ss = 0.f;
#pragma unroll 8
    for (int r = 0; r < 32; r++) {
        float x = g_hnew[(size_t)(r0 + r) * C + c];
        s += x; ss += x * x;
    }
    g_psum[blockIdx.x * C + c] = s;
    g_psq [blockIdx.x * C + c] = ss;
}

__global__ __launch_bounds__(256) void k_bn_final() {
    int c = threadIdx.x;
    float s = 0.f, ss = 0.f;
#pragma unroll 8
    for (int k = 0; k < 256; k++) {
        s  += g_psum[k * C + c];
        ss += g_psq [k * C + c];
    }
    float m = s * (1.f / (float)ROWS);
    float v = ss * (1.f / (float)ROWS) - m * m;
    v = v > 0.f ? v : 0.f;
    g_mean[c] = m;
    g_rstd[c] = rsqrtf(v + 1e-5f);
}

// ============================================================
// K6: normalize + affine + ELU
// ============================================================
__global__ __launch_bounds__(256) void k_norm(const float* __restrict__ gamma,
                                              const float* __restrict__ beta,
                                              float* __restrict__ out) {
    int idx = blockIdx.x * 256 + threadIdx.x;
    int c = (idx & 63) * 4;
    float4 x = ((const float4*)g_hnew)[idx];
    float4 y;
    y.x = (x.x - g_mean[c + 0]) * g_rstd[c + 0] * gamma[c + 0] + beta[c + 0];
    y.y = (x.y - g_mean[c + 1]) * g_rstd[c + 1] * gamma[c + 1] + beta[c + 1];
    y.z = (x.z - g_mean[c + 2]) * g_rstd[c + 2] * gamma[c + 2] + beta[c + 2];
    y.w = (x.w - g_mean[c + 3]) * g_rstd[c + 3] * gamma[c + 3] + beta[c + 3];
    y.x = y.x > 0.f ? y.x : expm1f(y.x);
    y.y = y.y > 0.f ? y.y : expm1f(y.y);
    y.z = y.z > 0.f ? y.z : expm1f(y.z);
    y.w = y.w > 0.f ? y.w : expm1f(y.w);
    ((float4*)out)[idx] = y;
}

// ============================================================
extern "C" void kernel_launch(void* const* d_in, const int* in_sizes, int n_in,
                              void* d_out, int out_size) {
    const float* h     = (const float*)d_in[0];
    const float* W     = (const float*)d_in[1];
    const float* a     = (const float*)d_in[2];
    const float* gamma = (const float*)d_in[3];
    const float* beta  = (const float*)d_in[4];
    const int*   adj   = (const int*)d_in[5];
    float* out = (float*)d_out;

    k_gemm<<<ROWS / 32, 256>>>(h, W);
    k_srcdst<<<Bn * Nn * Hn / 8, 256>>>(a);
    k_maskexp<<<Nn * 32 * 4 / 256, 256>>>(adj);
    dim3 g(Nn / 128, Hn, Bn);      // 16 x 4 x 4 = 256 blocks, launch #4 for ncu
    k_attn<<<g, 128>>>();
    k_bn_partial<<<256, 256>>>();
    k_bn_final<<<1, 256>>>();
    k_norm<<<ROWS * C / 4 / 256, 256>>>(gamma, beta, out);
}